// round 11
// baseline (speedup 1.0000x reference)
#include <cuda_runtime.h>
#include <cuda_fp16.h>
#include <cstdint>
#include <cstddef>

// ============================================================================
// Windowed self-attention via mma.sync.m16n8k16 fp16 (split-fp32, fp32 acc).
// S-equiv = (x M^T + r) x^T  (M = Wq^T Wk, r = bq Wk; row-consts cancel in
// softmax). 4 GEMMs/window, re-sequenced so no two big accumulators coexist:
//   G3: vT = Wvh xh^T + bv (1-term)   [independent of t -> runs first]
//   G1: t  = x M^T + r     (3-term)
//   G2: S  = t x^T         (3-term, A = t register fragments)
//   G4: O  = Ph vT^T       (1-term, overlapped with next window's x load)
// 8 warps x 16 rows, 256 thr, persistent CTAs, 2 barriers/window.
// ============================================================================

#define WIN 128
// smem layout (bytes from 1KB-aligned base)
#define XH   0
#define XL   32768
#define MH   65536
#define WVH  131072
#define VTB  163840
#define OFF_BV 196608
#define OFF_R  197120
#define SMEM_PAYLOAD 197632
#define SMEM_BYTES (SMEM_PAYLOAD + 1024)

__device__ __forceinline__ uint32_t smem_u32(const void* p) {
    uint32_t a;
    asm("{ .reg .u64 t; cvta.to.shared.u64 t, %1; cvt.u32.u64 %0, t; }" : "=r"(a) : "l"(p));
    return a;
}

// Tile: 128 rows x 128 fp16 (256B/row, 16 chunks of 16B), XOR-swizzled.
__device__ __forceinline__ uint32_t toff(int row, int byteCol) {
    int chunk = byteCol >> 4;
    return (uint32_t)(row * 256 + (((chunk ^ (row & 7)) << 4) | (byteCol & 15)));
}

__device__ __forceinline__ uint32_t pack2h(__half a, __half b) {
    return (uint32_t)__half_as_ushort(a) | ((uint32_t)__half_as_ushort(b) << 16);
}

__device__ __forceinline__ void ldsm4(uint32_t r[4], uint32_t addr) {
    asm volatile("ldmatrix.sync.aligned.m8n8.x4.shared.b16 {%0,%1,%2,%3}, [%4];"
                 : "=r"(r[0]), "=r"(r[1]), "=r"(r[2]), "=r"(r[3]) : "r"(addr));
}

__device__ __forceinline__ void mma16816(float* c, const uint32_t a[4],
                                         uint32_t b0, uint32_t b1) {
    asm volatile(
        "mma.sync.aligned.m16n8k16.row.col.f32.f16.f16.f32 "
        "{%0,%1,%2,%3}, {%4,%5,%6,%7}, {%8,%9}, {%0,%1,%2,%3};"
        : "+f"(c[0]), "+f"(c[1]), "+f"(c[2]), "+f"(c[3])
        : "r"(a[0]), "r"(a[1]), "r"(a[2]), "r"(a[3]), "r"(b0), "r"(b1));
}

// Pre-split + pre-swizzled images: [M^T hi, M^T lo, Wv hi]
__device__ __align__(16) __half g_img[3 * 16384];
__device__ float g_r[128];

// ---- fused prep: M image, Wv image, r vector ----
__global__ void prep_all(const float* __restrict__ Wq, const float* __restrict__ bq,
                         const float* __restrict__ Wk, const float* __restrict__ Wv) {
    __shared__ float wkcol[128];
    __shared__ float red[4];
    int f = blockIdx.x, e = threadIdx.x;
    wkcol[e] = Wk[e * 128 + f];
    __syncthreads();
    // M[e,f] = sum_d Wq[d,e] Wk[d,f]  -> B-image row f, col e
    float acc = 0.0f;
#pragma unroll 8
    for (int d = 0; d < 128; d++)
        acc += Wq[d * 128 + e] * wkcol[d];
    uint32_t o = toff(f, e * 2) >> 1;
    {
        __half h = __float2half_rn(acc);
        g_img[o] = h;
        g_img[16384 + o] = __float2half_rn(acc - __half2float(h));
    }
    // Wv hi image: row f(=d), col e
    g_img[2 * 16384 + o] = __float2half_rn(Wv[f * 128 + e]);
    // r[f] = sum_d bq[d] Wk[d,f]
    float p = bq[e] * wkcol[e];
#pragma unroll
    for (int m = 16; m >= 1; m >>= 1) p += __shfl_xor_sync(0xffffffffu, p, m);
    if ((e & 31) == 0) red[e >> 5] = p;
    __syncthreads();
    if (e == 0) g_r[f] = red[0] + red[1] + red[2] + red[3];
}

// copy pre-swizzled 32KB image into smem (256 threads)
__device__ __forceinline__ void copy_img32(char* dst, int imgIdx, int tid) {
    const uint4* s4 = reinterpret_cast<const uint4*>(g_img + (size_t)imgIdx * 16384);
    uint4* d4 = reinterpret_cast<uint4*>(dst);
#pragma unroll
    for (int i = 0; i < 8; i++) d4[tid + i * 256] = s4[tid + i * 256];
}

// load + split one window of x into XH/XL (all 256 threads)
__device__ __forceinline__ void load_x(const float* __restrict__ xw, char* smem, int tid) {
#pragma unroll
    for (int i = 0; i < 16; i++) {
        int idx4 = i * 256 + tid;
        int row = idx4 >> 5, col4 = idx4 & 31;
        float4 v = reinterpret_cast<const float4*>(xw)[idx4];
        __half h0 = __float2half_rn(v.x), h1 = __float2half_rn(v.y);
        __half h2 = __float2half_rn(v.z), h3 = __float2half_rn(v.w);
        uint32_t off = toff(row, col4 * 8);
        *reinterpret_cast<uint2*>(smem + XH + off) =
            make_uint2(pack2h(h0, h1), pack2h(h2, h3));
        *reinterpret_cast<uint2*>(smem + XL + off) = make_uint2(
            pack2h(__float2half_rn(v.x - __half2float(h0)),
                   __float2half_rn(v.y - __half2float(h1))),
            pack2h(__float2half_rn(v.z - __half2float(h2)),
                   __float2half_rn(v.w - __half2float(h3))));
    }
}

// ---- 3-term GEMM: A smem hi/lo (aBase, aBase+32KB), B smem hi/lo ----
__device__ __forceinline__ void gemm3_sa(float (&c)[16][4],
                                         uint32_t aBase, uint32_t bBase,
                                         int arow, int acb, int brl, int bcb) {
#pragma unroll
    for (int nt = 0; nt < 16; nt++)
#pragma unroll
        for (int i = 0; i < 4; i++) c[nt][i] = 0.0f;
#pragma unroll 1
    for (int kt = 0; kt < 8; kt++) {
        uint32_t ah[4], al[4];
        {
            uint32_t off = (uint32_t)(arow * 256 + (((kt * 2 + acb) ^ (arow & 7)) << 4));
            ldsm4(ah, aBase + off);
            ldsm4(al, aBase + 32768u + off);
        }
#pragma unroll
        for (int ng = 0; ng < 8; ng++) {
            int brow = ng * 16 + brl;
            uint32_t boff = (uint32_t)(brow * 256 + (((kt * 2 + bcb) ^ (brow & 7)) << 4));
            uint32_t bh[4], bl[4];
            ldsm4(bh, bBase + boff);
            ldsm4(bl, bBase + 32768u + boff);
#pragma unroll
            for (int s = 0; s < 2; s++) {
                float* cc = c[ng * 2 + s];
                mma16816(cc, ah, bh[2 * s], bh[2 * s + 1]);
                mma16816(cc, ah, bl[2 * s], bl[2 * s + 1]);
                mma16816(cc, al, bh[2 * s], bh[2 * s + 1]);
            }
        }
    }
}

// ---- 3-term GEMM: A register fragments (hi/lo), B smem hi/lo ----
__device__ __forceinline__ void gemm3_ra(float (&c)[16][4],
                                         const uint32_t (&th)[16][2],
                                         const uint32_t (&tl)[16][2],
                                         uint32_t bBase, int brl, int bcb) {
#pragma unroll
    for (int nt = 0; nt < 16; nt++)
#pragma unroll
        for (int i = 0; i < 4; i++) c[nt][i] = 0.0f;
#pragma unroll
    for (int kt = 0; kt < 8; kt++) {
        uint32_t ah[4] = {th[2 * kt][0], th[2 * kt][1], th[2 * kt + 1][0], th[2 * kt + 1][1]};
        uint32_t al[4] = {tl[2 * kt][0], tl[2 * kt][1], tl[2 * kt + 1][0], tl[2 * kt + 1][1]};
#pragma unroll
        for (int ng = 0; ng < 8; ng++) {
            int brow = ng * 16 + brl;
            uint32_t boff = (uint32_t)(brow * 256 + (((kt * 2 + bcb) ^ (brow & 7)) << 4));
            uint32_t bh[4], bl[4];
            ldsm4(bh, bBase + boff);
            ldsm4(bl, bBase + 32768u + boff);
#pragma unroll
            for (int s = 0; s < 2; s++) {
                float* cc = c[ng * 2 + s];
                mma16816(cc, ah, bh[2 * s], bh[2 * s + 1]);
                mma16816(cc, ah, bl[2 * s], bl[2 * s + 1]);
                mma16816(cc, al, bh[2 * s], bh[2 * s + 1]);
            }
        }
    }
}

// ---- 1-term GEMM: A smem single image, B smem single image ----
__device__ __forceinline__ void gemm1_sa(float (&c)[16][4],
                                         uint32_t aBase, uint32_t bBase,
                                         int arow, int acb, int brl, int bcb) {
#pragma unroll
    for (int nt = 0; nt < 16; nt++)
#pragma unroll
        for (int i = 0; i < 4; i++) c[nt][i] = 0.0f;
#pragma unroll 1
    for (int kt = 0; kt < 8; kt++) {
        uint32_t ah[4];
        {
            uint32_t off = (uint32_t)(arow * 256 + (((kt * 2 + acb) ^ (arow & 7)) << 4));
            ldsm4(ah, aBase + off);
        }
#pragma unroll
        for (int ng = 0; ng < 8; ng++) {
            int brow = ng * 16 + brl;
            uint32_t boff = (uint32_t)(brow * 256 + (((kt * 2 + bcb) ^ (brow & 7)) << 4));
            uint32_t bh[4];
            ldsm4(bh, bBase + boff);
#pragma unroll
            for (int s = 0; s < 2; s++)
                mma16816(c[ng * 2 + s], ah, bh[2 * s], bh[2 * s + 1]);
        }
    }
}

// ---- 1-term GEMM: A register fragments (hi only), B smem single image ----
__device__ __forceinline__ void gemm1_ra(float (&c)[16][4],
                                         const uint32_t (&th)[16][2],
                                         uint32_t bBase, int brl, int bcb) {
#pragma unroll
    for (int nt = 0; nt < 16; nt++)
#pragma unroll
        for (int i = 0; i < 4; i++) c[nt][i] = 0.0f;
#pragma unroll
    for (int kt = 0; kt < 8; kt++) {
        uint32_t ah[4] = {th[2 * kt][0], th[2 * kt][1], th[2 * kt + 1][0], th[2 * kt + 1][1]};
#pragma unroll
        for (int ng = 0; ng < 8; ng++) {
            int brow = ng * 16 + brl;
            uint32_t boff = (uint32_t)(brow * 256 + (((kt * 2 + bcb) ^ (brow & 7)) << 4));
            uint32_t bh[4];
            ldsm4(bh, bBase + boff);
#pragma unroll
            for (int s = 0; s < 2; s++)
                mma16816(c[ng * 2 + s], ah, bh[2 * s], bh[2 * s + 1]);
        }
    }
}

// pack C fragments into hi-only fp16 A-fragments (for P)
__device__ __forceinline__ void pack_hi(const float (&c)[16][4], uint32_t (&h)[16][2]) {
#pragma unroll
    for (int nt = 0; nt < 16; nt++)
#pragma unroll
        for (int j = 0; j < 2; j++)
            h[nt][j] = pack2h(__float2half_rn(c[nt][2 * j]),
                              __float2half_rn(c[nt][2 * j + 1]));
}

// pack C fragments into hi/lo fp16 A-fragments, adding per-column bias r (t)
__device__ __forceinline__ void pack_split_bias(const float (&c)[16][4],
                                                uint32_t (&h)[16][2], uint32_t (&l)[16][2],
                                                const float* sr, int cq) {
#pragma unroll
    for (int nt = 0; nt < 16; nt++) {
        float rA = sr[nt * 8 + cq], rB = sr[nt * 8 + cq + 1];
#pragma unroll
        for (int j = 0; j < 2; j++) {
            float v0 = c[nt][2 * j] + rA, v1 = c[nt][2 * j + 1] + rB;
            __half h0 = __float2half_rn(v0), h1 = __float2half_rn(v1);
            h[nt][j] = pack2h(h0, h1);
            l[nt][j] = pack2h(__float2half_rn(v0 - __half2float(h0)),
                              __float2half_rn(v1 - __half2float(h1)));
        }
    }
}

__global__ void __launch_bounds__(256, 1)
win_attn(const float* __restrict__ x, const float* __restrict__ bv,
         float* __restrict__ out, int nwin) {
    extern __shared__ char smem_raw[];
    uint32_t sraw = smem_u32(smem_raw);
    uint32_t sb = (sraw + 1023u) & ~1023u;
    char* smem = smem_raw + (sb - sraw);

    const int tid = threadIdx.x, wid = tid >> 5, lane = tid & 31;

    float* sbv = reinterpret_cast<float*>(smem + OFF_BV);
    float* sr  = reinterpret_cast<float*>(smem + OFF_R);
    if (tid < 128) {
        sbv[tid] = bv[tid];
        sr[tid] = g_r[tid];
    }
    // resident weight images: M hi, M lo, Wv hi
    copy_img32(smem + MH, 0, tid);
    copy_img32(smem + MH + 32768, 1, tid);
    copy_img32(smem + WVH, 2, tid);

    // ldmatrix lane mappings
    const int arl = (lane & 7) + ((lane >> 3) & 1) * 8, acb = (lane >> 4) & 1;
    const int brl = (lane & 7) + ((lane >> 4) & 1) * 8, bcb = (lane >> 3) & 1;
    const int rq = lane >> 2, cq = 2 * (lane & 3);
    const int rowBase = wid * 16;
    const int arow = rowBase + arl;

    float c[16][4];
    uint32_t fh[16][2], fl[16][2];   // A-fragments: t (hi/lo), then P (hi)

    int w = blockIdx.x;
    if (w < nwin) load_x(x + (size_t)w * (WIN * 128), smem, tid);
    __syncthreads();                     // x(w0), images, biases ready

    while (w < nwin) {
        // ---- G3 (1-term): vT = Wvh xh^T ; +bv row ; -> VTB ----
        gemm1_sa(c, sb + WVH, sb + XH, arow, acb, brl, bcb);
#pragma unroll
        for (int h = 0; h < 2; h++) {
            int row = rowBase + h * 8 + rq;
            float br = sbv[row];
#pragma unroll
            for (int nt = 0; nt < 16; nt++) {
                int col = nt * 8 + cq;
                *reinterpret_cast<uint32_t*>(smem + VTB + toff(row, col * 2)) =
                    pack2h(__float2half_rn(c[nt][2 * h] + br),
                           __float2half_rn(c[nt][2 * h + 1] + br));
            }
        }

        // ---- G1 (3-term): t = x M^T ; t += r ; -> register fragments ----
        gemm3_sa(c, sb + XH, sb + MH, arow, acb, brl, bcb);
        pack_split_bias(c, fh, fl, sr, cq);

        // ---- G2 (3-term): S = t x^T (A = t regs, B = XH/XL) ----
        gemm3_ra(c, fh, fl, sb + XH, brl, bcb);

        // softmax on c -> P fragments (hi only)
#pragma unroll
        for (int h = 0; h < 2; h++) {
            float m = -1e30f;
#pragma unroll
            for (int nt = 0; nt < 16; nt++)
                m = fmaxf(m, fmaxf(c[nt][2 * h], c[nt][2 * h + 1]));
            m = fmaxf(m, __shfl_xor_sync(0xffffffffu, m, 1));
            m = fmaxf(m, __shfl_xor_sync(0xffffffffu, m, 2));
            float s = 0.0f;
#pragma unroll
            for (int nt = 0; nt < 16; nt++) {
                float e0 = __expf(c[nt][2 * h] - m);
                float e1 = __expf(c[nt][2 * h + 1] - m);
                c[nt][2 * h] = e0;
                c[nt][2 * h + 1] = e1;
                s += e0 + e1;
            }
            s += __shfl_xor_sync(0xffffffffu, s, 1);
            s += __shfl_xor_sync(0xffffffffu, s, 2);
            float inv = 1.0f / s;
#pragma unroll
            for (int nt = 0; nt < 16; nt++) {
                c[nt][2 * h] *= inv;
                c[nt][2 * h + 1] *= inv;
            }
        }
        pack_hi(c, fh);                  // P fragments (hi only)
        __syncthreads();                 // (2) vT visible; XH/XL dead everywhere

        // ---- overlap: load x for next window while G4 runs ----
        int wn = w + gridDim.x;
        if (wn < nwin) load_x(x + (size_t)wn * (WIN * 128), smem, tid);

        // ---- G4 (1-term): O = Ph vT^T -> out ----
        gemm1_ra(c, fh, sb + VTB, brl, bcb);
        {
            float* outw = out + (size_t)w * (WIN * 128);
#pragma unroll
            for (int h = 0; h < 2; h++) {
                int row = rowBase + h * 8 + rq;
#pragma unroll
                for (int nt = 0; nt < 16; nt++) {
                    int col = nt * 8 + cq;
                    *reinterpret_cast<float2*>(outw + row * 128 + col) =
                        make_float2(c[nt][2 * h], c[nt][2 * h + 1]);
                }
            }
        }
        __syncthreads();                 // (1) new x ready; VTB dead

        w = wn;
    }
}

extern "C" void kernel_launch(void* const* d_in, const int* in_sizes, int n_in,
                              void* d_out, int out_size) {
    const float* x  = (const float*)d_in[0];
    const float* Wq = (const float*)d_in[1];
    const float* bq = (const float*)d_in[2];
    const float* Wk = (const float*)d_in[3];
    const float* Wv = (const float*)d_in[5];
    const float* bv = (const float*)d_in[6];
    float* out = (float*)d_out;

    int nwin = in_sizes[0] / (WIN * 128);

    prep_all<<<128, 128>>>(Wq, bq, Wk, Wv);

    cudaFuncSetAttribute(win_attn, cudaFuncAttributeMaxDynamicSharedMemorySize, SMEM_BYTES);
    int grid = nwin < 148 ? nwin : 148;
    win_attn<<<grid, 256, SMEM_BYTES>>>(x, bv, out, nwin);
}